// round 15
// baseline (speedup 1.0000x reference)
#include <cuda_runtime.h>
#include <cuda_fp16.h>
#include <cstdint>
#include <cstddef>

#define BATCH 8
#define CCH   512
#define M2    1024          // 2*C rows of P
#define KDIM  4096
#define NSTAGES 2
#define IMG16 16384                     // one 128-row fp16 level image (16KB)
#define PAIRBLK 65536                   // per (b,pair,kb): {h_lo,h_hi,m_lo,m_hi}
#define STAGE_BYTES 98304               // B(64K) + A(32K)
#define NKB   (KDIM / 64)               // 64 k-blocks of 64 elems
#define NSPLIT_CTAS 148                 // CTAs carrying split shares (all wave-1 resident)

// idesc kind::f16 fp16: dtype F32 (1<<4) | (N/8)<<17 | (M/16)<<24  (M=128)
#define IDESC_N256 0x08400010u
#define IDESC_N128 0x08200010u

#if defined(__CUDA_ARCH__) && (defined(__CUDA_ARCH_FEAT_SM103_ALL) || defined(__CUDA_ARCH_FEAT_SM100_ALL) || defined(__CUDA_ARCH_FEAT_SM101_ALL) || defined(__CUDA_ARCH_FEAT_SM110_ALL))
#define TC_OK 1
#else
#define TC_OK 0
#endif

// ---------------- scratch (static device globals; no allocation) ----------------
__device__ uint32_t       g_pack[(size_t)BATCH * 4 * NKB * 16384];  // 134 MB
__device__ float          g_S[(size_t)BATCH * M2 * M2];             // 32 MB  S = P P^T
__device__ float          g_w[(size_t)BATCH * CCH * CCH];
__device__ unsigned short g_idx[(size_t)BATCH * CCH * CCH];
__device__ int            g_cnt[BATCH * CCH];
__device__ int            g_kbrdy[NKB];                             // split->syrk flags

// heavy tiles (16/batch): 4x T1 (i=2k, colpair k, A inside B) + 12x inter.
// flags bit0 wlo, bit1 mlo, bit2 whi, bit3 mhi.
__constant__ unsigned char c_hI[16]  = {0,2,4,6, 2,3,4,5, 4,5,6,7, 6,7,6,7};
__constant__ unsigned char c_hJ[16]  = {0,1,2,3, 0,0,0,0, 1,1,0,0, 1,1,2,2};
__constant__ unsigned char c_hFL[16] = {0xD,0xD,0xD,0xD, 0xF,0xF,0xF,0xF,
                                        0xF,0xF,0xF,0xF, 0xF,0xF,0xF,0xF};

// ======================= helpers =======================
__device__ __forceinline__ uint32_t smem_u32(const void* p) {
    uint32_t a;
    asm("{ .reg .u64 t; cvta.to.shared.u64 t, %1; cvt.u32.u64 %0, t; }" : "=r"(a) : "l"(p));
    return a;
}

__device__ __forceinline__ void cvt2p(float e0, float e1, uint32_t& hw, uint32_t& mw) {
    asm("cvt.rn.f16x2.f32 %0, %1, %2;" : "=r"(hw) : "f"(e1), "f"(e0));
    const __half2 hp = *reinterpret_cast<const __half2*>(&hw);
    const float2 hf = __half22float2(hp);
    const float r0 = e0 - hf.x, r1 = e1 - hf.y;
    asm("cvt.rn.f16x2.f32 %0, %1, %2;" : "=r"(mw) : "f"(r1), "f"(r0));
}

// =======================================================================
// Kernel Z: reset split-ready counters (must precede fused kernel each run)
// =======================================================================
__global__ void zero_kernel() { g_kbrdy[threadIdx.x] = 0; }

#if TC_OK
__device__ __forceinline__ void mbar_init(uint32_t a, uint32_t cnt) {
    asm volatile("mbarrier.init.shared.b64 [%0], %1;" :: "r"(a), "r"(cnt) : "memory");
}
__device__ __forceinline__ void mbar_inval(uint32_t a) {
    asm volatile("mbarrier.inval.shared.b64 [%0];" :: "r"(a) : "memory");
}
__device__ __forceinline__ void mbar_expect_tx(uint32_t a, uint32_t bytes) {
    asm volatile("mbarrier.arrive.expect_tx.shared.b64 _, [%0], %1;" :: "r"(a), "r"(bytes) : "memory");
}
__device__ __forceinline__ void mbar_wait(uint32_t a, uint32_t parity) {
    asm volatile(
        "{\n\t.reg .pred P;\n\t"
        "W%=:\n\t"
        "mbarrier.try_wait.parity.acquire.cta.shared::cta.b64 P, [%0], %1, 0x989680;\n\t"
        "@P bra.uni D%=;\n\t"
        "bra.uni W%=;\n\t"
        "D%=:\n\t}"
        :: "r"(a), "r"(parity) : "memory");
}
__device__ __forceinline__ void bulk_g2s(uint32_t dst, const void* src, uint32_t bytes, uint32_t mbar) {
    asm volatile(
        "cp.async.bulk.shared::cta.global.mbarrier::complete_tx::bytes [%0], [%1], %2, [%3];"
        :: "r"(dst), "l"(src), "r"(bytes), "r"(mbar) : "memory");
}
__device__ __forceinline__ uint64_t make_desc_sw128(uint32_t addr) {
    return ((uint64_t)2 << 61) | ((uint64_t)1 << 46) | ((uint64_t)64 << 32) |
           ((uint64_t)1 << 16) | (((uint64_t)(addr >> 4)) & 0x3FFF);
}
__device__ __forceinline__ void mma_f16(uint32_t d, uint64_t ad, uint64_t bd, uint32_t idesc, uint32_t en) {
    asm volatile(
        "{\n\t.reg .pred p;\n\t"
        "setp.ne.u32 p, %5, 0;\n\t"
        "tcgen05.mma.cta_group::1.kind::f16 [%0], %1, %2, %3, {%4,%4,%4,%4}, p;\n\t}"
        :: "r"(d), "l"(ad), "l"(bd), "r"(idesc), "r"(0u), "r"(en) : "memory");
}
__device__ __forceinline__ void tc_commit(uint32_t mbar) {
    asm volatile(
        "tcgen05.commit.cta_group::1.mbarrier::arrive::one.shared::cluster.b64 [%0];"
        :: "r"(mbar) : "memory");
}
__device__ __forceinline__ void flag_release_add(int* p) {
    asm volatile("red.release.gpu.global.add.s32 [%0], 1;" :: "l"(p) : "memory");
}
__device__ __forceinline__ void flag_wait(const int* p, int target) {
    int v;
    do {
        asm volatile("ld.acquire.gpu.global.s32 %0, [%1];" : "=r"(v) : "l"(p) : "memory");
        if (v >= target) break;
        asm volatile("nanosleep.u32 128;");
    } while (true);
}
#endif

// =======================================================================
// Kernel A (fused): per-CTA roles (256 threads):
//   t0       : bulk-copy producer (spins on g_kbrdy[kb] before stage kb)
//   t32      : MMA issuer, 3 terms (hh, hm, mh)
//   warps 4-7: cooperative kb-major split of x -> g_pack (CTAs 0..147)
//   warps 0-3: TMEM epilogue (named barrier 2)
// 160 CTAs: 128 heavy 128x256 tiles first, 32 light 128x128 diag tiles.
// =======================================================================
__global__ __launch_bounds__(256, 1) void syrk_fused_kernel(const float* __restrict__ x) {
#if TC_OK
    extern __shared__ char smem[];
    const uint32_t sb = smem_u32(smem);
    const uint32_t tb = (sb + 1023u) & ~1023u;
    const uint32_t ctl = tb + NSTAGES * STAGE_BYTES;
    const uint32_t mb_full  = ctl + 16;                   // 2 x 8B
    const uint32_t mb_empty = ctl + 16 + 16;              // 2 x 8B
    const uint32_t mb_done  = ctl + 16 + 32;

    const int tid = threadIdx.x;
    const int wid = tid >> 5, lid = tid & 31;

    const int bx = blockIdx.x;
    int b, i, J, fl, typ;      // typ: 0 = T1 heavy, 1 = inter heavy, 2 = light
    if (bx < 128) {
        b = bx >> 4;
        const int t = bx & 15;
        i = c_hI[t]; J = c_hJ[t]; fl = c_hFL[t];
        typ = (t < 4) ? 0 : 1;
    } else {
        const int q = bx - 128;
        b = q >> 2;
        i = (q & 3) * 2 + 1;
        J = i;
        fl = 0x1;
        typ = 2;
    }
    const bool heavy = (typ <= 1);
    const uint32_t idesc = heavy ? IDESC_N256 : IDESC_N128;
    const uint32_t txbytes = (typ == 1) ? 98304u : (typ == 0 ? 65536u : 32768u);

    if (wid == 0) {
        asm volatile("tcgen05.alloc.cta_group::1.sync.aligned.shared::cta.b32 [%0], %1;"
                     :: "r"(ctl), "r"(256u) : "memory");
    }
    if (tid == 0) {
        for (int s = 0; s < NSTAGES; s++) { mbar_init(mb_full + s * 8, 1); mbar_init(mb_empty + s * 8, 1); }
        mbar_init(mb_done, 1);
        asm volatile("fence.proxy.async.shared::cta;" ::: "memory");
    }
    __syncthreads();

    uint32_t tmem;
    asm volatile("ld.shared.b32 %0, [%1];" : "=r"(tmem) : "r"(ctl));

    if (tid >= 128) {
        // ================= splitters (warps 4-7), CTAs 0..147 only =================
        if (bx < NSPLIT_CTAS) {
            const int wt = bx * 128 + (tid - 128);        // global splitter id
            for (int kb = 0; kb < NKB; kb++) {
                // units per kb: 32768 = (b,pair)(32) x row(256) x grp(4)
                for (int u = wt; u < 32768; u += NSPLIT_CTAS * 128) {
                    const int bp = u >> 10;
                    const int ub = bp >> 2, pair = bp & 3;
                    const int rg = u & 1023;
                    const int row = rg >> 2, grp = rg & 3;
                    const int grow = pair * 256 + row;    // 0..1023
                    size_t src;
                    if (grow < CCH) src = ((size_t)ub * CCH + grow) * KDIM;
                    else            src = ((size_t)(BATCH + ub) * CCH + (grow - CCH)) * KDIM;
                    src += (size_t)kb * 64 + grp * 16;
                    char* blk = (char*)g_pack
                        + ((((size_t)ub * 4 + pair) * NKB) + kb) * (size_t)PAIRBLK
                        + (size_t)(row >> 7) * IMG16;
                    const int r = row & 127;
                    #pragma unroll
                    for (int g = 0; g < 2; g++) {
                        const float4 v0 = *(const float4*)(x + src + g * 8);
                        const float4 v1 = *(const float4*)(x + src + g * 8 + 4);
                        uint4 hv, mv;
                        cvt2p(v0.x, v0.y, hv.x, mv.x);
                        cvt2p(v0.z, v0.w, hv.y, mv.y);
                        cvt2p(v1.x, v1.y, hv.z, mv.z);
                        cvt2p(v1.z, v1.w, hv.w, mv.w);
                        const uint32_t byte_off = (uint32_t)r * 128u + (uint32_t)(grp * 2 + g) * 16u;
                        const uint32_t sw = byte_off ^ ((byte_off >> 3) & 0x70u);
                        *(uint4*)(blk + sw)             = hv;
                        *(uint4*)(blk + sw + 2 * IMG16) = mv;
                    }
                }
                asm volatile("bar.sync 1, 128;" ::: "memory");
                if (tid == 128) flag_release_add(&g_kbrdy[kb]);
            }
        }
    } else if (tid == 0) {
        // ================= producer =================
        const char* PB = (const char*)g_pack +
            (((size_t)b * 4 + (heavy ? J : (i >> 1))) * NKB) * (size_t)PAIRBLK;
        const char* PA = (const char*)g_pack +
            (((size_t)b * 4 + (i >> 1)) * NKB) * (size_t)PAIRBLK;
        const uint32_t ahalf = (uint32_t)(i & 1) * IMG16;
        int ph[NSTAGES] = {0, 0};
        for (int kb = 0; kb < NKB; kb++) {
            const int s = kb & 1;
            flag_wait(&g_kbrdy[kb], NSPLIT_CTAS);
            if (kb >= NSTAGES) { mbar_wait(mb_empty + s * 8, ph[s]); ph[s] ^= 1; }
            const uint32_t st = tb + s * STAGE_BYTES;
            const uint32_t fb = mb_full + s * 8;
            mbar_expect_tx(fb, txbytes);
            if (typ == 2) {
                bulk_g2s(st,          PB + (size_t)kb * PAIRBLK + IMG16,     IMG16, fb);
                bulk_g2s(st + 32768,  PB + (size_t)kb * PAIRBLK + 3 * IMG16, IMG16, fb);
            } else {
                bulk_g2s(st, PB + (size_t)kb * PAIRBLK, PAIRBLK, fb);     // B: h(32K)+m(32K)
                if (typ == 1) {
                    bulk_g2s(st + 65536, PA + (size_t)kb * PAIRBLK + ahalf,             IMG16, fb);
                    bulk_g2s(st + 81920, PA + (size_t)kb * PAIRBLK + 2 * IMG16 + ahalf, IMG16, fb);
                }
            }
        }
    } else if (tid == 32) {
        // ================= MMA issuer: 3 terms (hh, hm, mh) =================
        int ph[NSTAGES] = {0, 0};
        uint32_t en = 0;
        for (int kb = 0; kb < NKB; kb++) {
            const int s = kb & 1;
            mbar_wait(mb_full + s * 8, ph[s]); ph[s] ^= 1;
            const uint32_t st = tb + s * STAGE_BYTES;
            const uint64_t dBh = make_desc_sw128(st);
            const uint64_t dBm = make_desc_sw128(st + 32768);
            const uint64_t dAh = (typ == 1) ? make_desc_sw128(st + 65536) : dBh;
            const uint64_t dAm = (typ == 1) ? make_desc_sw128(st + 81920) : dBm;
            #pragma unroll
            for (int k = 0; k < 4; k++) {
                const uint64_t o = k * 2;
                mma_f16(tmem, dAh + o, dBh + o, idesc, en); en = 1;
                mma_f16(tmem, dAh + o, dBm + o, idesc, 1);
                mma_f16(tmem, dAm + o, dBh + o, idesc, 1);
            }
            tc_commit(mb_empty + s * 8);
        }
        tc_commit(mb_done);
    }

    // ---------------- epilogue (warps 0-3 only; named barrier 2) ----------------
    mbar_wait(mb_done, 0);
    asm volatile("tcgen05.fence::after_thread_sync;" ::: "memory");

    if (tid < 128) {
        const size_t Sb = (size_t)b * M2 * M2;
        const int r0 = i * 128;
        const int colbase = heavy ? J * 256 : i * 128;
        const int nch = heavy ? 8 : 4;
        const int row = r0 + wid * 32 + lid;
        float* trsp = (float*)(smem + (tb - sb));

        for (int cb = 0; cb < nch; cb++) {
            const int half = heavy ? (cb >> 2) : 0;
            const int wbit = (fl >> (half * 2)) & 1;
            const int mbit = (fl >> (half * 2 + 1)) & 1;
            const int c0 = colbase + cb * 32;

            uint32_t d[32];
            asm volatile(
                "tcgen05.ld.sync.aligned.32x32b.x32.b32 "
                "{%0,%1,%2,%3,%4,%5,%6,%7,%8,%9,%10,%11,%12,%13,%14,%15,"
                "%16,%17,%18,%19,%20,%21,%22,%23,%24,%25,%26,%27,%28,%29,%30,%31}, [%32];"
                : "=r"(d[0]), "=r"(d[1]), "=r"(d[2]), "=r"(d[3]), "=r"(d[4]), "=r"(d[5]), "=r"(d[6]), "=r"(d[7]),
                  "=r"(d[8]), "=r"(d[9]), "=r"(d[10]), "=r"(d[11]), "=r"(d[12]), "=r"(d[13]), "=r"(d[14]), "=r"(d[15]),
                  "=r"(d[16]), "=r"(d[17]), "=r"(d[18]), "=r"(d[19]), "=r"(d[20]), "=r"(d[21]), "=r"(d[22]), "=r"(d[23]),
                  "=r"(d[24]), "=r"(d[25]), "=r"(d[26]), "=r"(d[27]), "=r"(d[28]), "=r"(d[29]), "=r"(d[30]), "=r"(d[31])
                : "r"(tmem + cb * 32));
            asm volatile("tcgen05.wait::ld.sync.aligned;" ::: "memory");

            if (wbit) {
                float* dst = g_S + Sb + (size_t)row * M2 + c0;
                #pragma unroll
                for (int q = 0; q < 8; q++) {
                    float4 v = make_float4(__uint_as_float(d[q * 4 + 0]), __uint_as_float(d[q * 4 + 1]),
                                           __uint_as_float(d[q * 4 + 2]), __uint_as_float(d[q * 4 + 3]));
                    *(float4*)(dst + q * 4) = v;
                }
            }
            if (mbit) {
                const int lr = wid * 32 + lid;
                #pragma unroll
                for (int j = 0; j < 32; j++)
                    trsp[j * 132 + lr] = __uint_as_float(d[j]);
                asm volatile("bar.sync 2, 128;" ::: "memory");
                const int mj = tid >> 2;
                const int ch = tid & 3;
                float* mdst = g_S + Sb + (size_t)(c0 + mj) * M2 + r0 + ch * 32;
                const float* msrc = trsp + mj * 132 + ch * 32;
                #pragma unroll
                for (int q = 0; q < 8; q++)
                    *(float4*)(mdst + q * 4) = *(const float4*)(msrc + q * 4);
                asm volatile("bar.sync 2, 128;" ::: "memory");
            }
        }
    }

    __syncthreads();
    if (tid == 0) {
        for (int s = 0; s < NSTAGES; s++) { mbar_inval(mb_full + s * 8); mbar_inval(mb_empty + s * 8); }
        mbar_inval(mb_done);
    }
    __syncthreads();
    if (wid == 0) {
        asm volatile("tcgen05.dealloc.cta_group::1.sync.aligned.b32 %0, %1;" :: "r"(tmem), "r"(256u));
    }
#endif
}

// =======================================================================
// Kernel B: warp-per-row softmax + compaction (no block barriers).
// =======================================================================
__global__ __launch_bounds__(256) void attn_kernel() {
    const int warp = threadIdx.x >> 5, lane = threadIdx.x & 31;
    const int r = blockIdx.x * 8 + warp;
    const int b = r >> 9, c = r & 511;

    const float* S0 = g_S + ((size_t)b * M2 + c) * M2;
    const float* S1 = g_S + ((size_t)b * M2 + CCH + c) * M2;

    float er[16], ei[16];
    float mer = -3.4e38f, mei = -3.4e38f;
    #pragma unroll
    for (int i = 0; i < 16; i++) {
        const int d = i * 32 + lane;
        const float s00 = S0[d];
        const float s0h = S0[CCH + d];
        const float s10 = S1[d];
        const float s1h = S1[CCH + d];
        er[i] = s00 - s1h;
        ei[i] = s0h + s10;
        mer = fmaxf(mer, er[i]);
        mei = fmaxf(mei, ei[i]);
    }
    #pragma unroll
    for (int o = 16; o > 0; o >>= 1) {
        mer = fmaxf(mer, __shfl_xor_sync(0xffffffffu, mer, o));
        mei = fmaxf(mei, __shfl_xor_sync(0xffffffffu, mei, o));
    }

    float sc[16];
    float smax = -3.4e38f;
    #pragma unroll
    for (int i = 0; i < 16; i++) {
        const float ar = mer - er[i];
        const float ai = mei - ei[i];
        sc[i] = ar * ar + ai * ai;
        smax = fmaxf(smax, sc[i]);
    }
    #pragma unroll
    for (int o = 16; o > 0; o >>= 1)
        smax = fmaxf(smax, __shfl_xor_sync(0xffffffffu, smax, o));

    float Z = 0.0f;
    #pragma unroll
    for (int i = 0; i < 16; i++) {
        sc[i] = expf(sc[i] - smax);
        Z += sc[i];
    }
    #pragma unroll
    for (int o = 16; o > 0; o >>= 1)
        Z += __shfl_xor_sync(0xffffffffu, Z, o);
    const float invZ = 1.0f / Z;

    int cntl = 0;
    #pragma unroll
    for (int i = 0; i < 16; i++) {
        sc[i] *= invZ;
        if (sc[i] > 1e-10f) cntl++;
    }
    int incl = cntl;
    #pragma unroll
    for (int o = 1; o < 32; o <<= 1) {
        const int v = __shfl_up_sync(0xffffffffu, incl, o);
        if (lane >= o) incl += v;
    }
    const int total = __shfl_sync(0xffffffffu, incl, 31);
    int pos = incl - cntl;
    const size_t lbase = (size_t)r * CCH;
    #pragma unroll
    for (int i = 0; i < 16; i++) {
        if (sc[i] > 1e-10f) {
            g_idx[lbase + pos] = (unsigned short)(i * 32 + lane);
            g_w[lbase + pos] = sc[i];
            pos++;
        }
    }
    if (lane == 0) g_cnt[r] = total;
}

// =======================================================================
// Kernel C: out = gamma * (sparse attention @ q) + x
// =======================================================================
__global__ __launch_bounds__(256) void apply_kernel(const float* __restrict__ x,
                                                    const float* __restrict__ gamma,
                                                    float* __restrict__ out) {
    const int r = blockIdx.x;
    const int b = r >> 9, c = r & 511;
    const int n = blockIdx.y * 1024 + threadIdx.x * 4;

    const int cnt = g_cnt[r];
    const float g = gamma[0];
    const size_t imagOff = (size_t)BATCH * CCH * KDIM;
    const float* xr = x;
    const float* xi = x + imagOff;

    float4 ar = make_float4(0.f, 0.f, 0.f, 0.f);
    float4 ai = make_float4(0.f, 0.f, 0.f, 0.f);
    const size_t lbase = (size_t)r * CCH;

    for (int i = 0; i < cnt; i++) {
        const int dch = g_idx[lbase + i];
        const float w = g_w[lbase + i];
        const size_t q = ((size_t)b * CCH + dch) * KDIM + n;
        const float4 qr = *(const float4*)(xr + q);
        const float4 qi = *(const float4*)(xi + q);
        ar.x += w * qr.x; ar.y += w * qr.y; ar.z += w * qr.z; ar.w += w * qr.w;
        ai.x += w * qi.x; ai.y += w * qi.y; ai.z += w * qi.z; ai.w += w * qi.w;
    }

    const size_t o = ((size_t)b * CCH + c) * KDIM + n;
    const float4 xrv = *(const float4*)(xr + o);
    const float4 xiv = *(const float4*)(xi + o);
    float4 orr = make_float4(g * ar.x + xrv.x, g * ar.y + xrv.y,
                             g * ar.z + xrv.z, g * ar.w + xrv.w);
    float4 oii = make_float4(g * ai.x + xiv.x, g * ai.y + xiv.y,
                             g * ai.z + xiv.z, g * ai.w + xiv.w);
    *(float4*)(out + o) = orr;
    *(float4*)(out + imagOff + o) = oii;
}

// =======================================================================
extern "C" void kernel_launch(void* const* d_in, const int* in_sizes, int n_in,
                              void* d_out, int out_size) {
    const float* x = (const float*)d_in[0];
    const float* gamma = (const float*)d_in[1];
    float* out = (float*)d_out;

    const int SMEM_DYN = 1024 + NSTAGES * STAGE_BYTES + 256;   // ~197.9 KB
    cudaFuncSetAttribute(syrk_fused_kernel, cudaFuncAttributeMaxDynamicSharedMemorySize, SMEM_DYN);

    zero_kernel<<<1, NKB>>>();
    syrk_fused_kernel<<<160, 256, SMEM_DYN>>>(x);
    attn_kernel<<<512, 256>>>();
    apply_kernel<<<dim3(BATCH * CCH, 4), 256>>>(x, gamma, out);
}

// round 16
// speedup vs baseline: 1.1227x; 1.1227x over previous
#include <cuda_runtime.h>
#include <cuda_fp16.h>
#include <cstdint>
#include <cstddef>

#define BATCH 8
#define CCH   512
#define M2    1024          // 2*C rows of P
#define KDIM  4096
#define NSTAGES 3
#define IMG16 16384                     // one 128-row fp16 level image (16KB)
#define PAIRBLK 65536                   // per (b,pair,kb): {h_lo,h_hi,m_lo,m_hi}
#define STAGE_BYTES 65536               // per CTA: A(h16+m16) + B(h16+m16)
#define NKB   (KDIM / 64)               // 64 k-blocks of 64 elems

// idesc kind::f16 fp16 cg2: dtype F32 (1<<4) | (N/8)<<17 | (M/16)<<24, M=256 N=256
#define IDESC_CG2 0x10400010u

#if defined(__CUDA_ARCH__) && (defined(__CUDA_ARCH_FEAT_SM103_ALL) || defined(__CUDA_ARCH_FEAT_SM100_ALL) || defined(__CUDA_ARCH_FEAT_SM101_ALL) || defined(__CUDA_ARCH_FEAT_SM110_ALL))
#define TC_OK 1
#else
#define TC_OK 0
#endif

// ---------------- scratch (static device globals; no allocation) ----------------
__device__ uint32_t       g_pack[(size_t)BATCH * 4 * NKB * 16384];  // 134 MB
__device__ float          g_S[(size_t)BATCH * M2 * M2];             // 32 MB  S = P P^T
__device__ float          g_w[(size_t)BATCH * CCH * CCH];
__device__ unsigned short g_idx[(size_t)BATCH * CCH * CCH];
__device__ int            g_cnt[BATCH * CCH];

// 10 pair-tiles per batch: (ti<=tj) over 4 rowblock-pairs
__constant__ unsigned char c_TI2[10] = {0,0,0,0,1,1,1,2,2,3};
__constant__ unsigned char c_TJ2[10] = {0,1,2,3,1,2,3,2,3,3};

// ======================= helpers =======================
__device__ __forceinline__ uint32_t smem_u32(const void* p) {
    uint32_t a;
    asm("{ .reg .u64 t; cvta.to.shared.u64 t, %1; cvt.u32.u64 %0, t; }" : "=r"(a) : "l"(p));
    return a;
}

__device__ __forceinline__ void cvt2p(float e0, float e1, uint32_t& hw, uint32_t& mw) {
    asm("cvt.rn.f16x2.f32 %0, %1, %2;" : "=r"(hw) : "f"(e1), "f"(e0));
    const __half2 hp = *reinterpret_cast<const __half2*>(&hw);
    const float2 hf = __half22float2(hp);
    const float r0 = e0 - hf.x, r1 = e1 - hf.y;
    asm("cvt.rn.f16x2.f32 %0, %1, %2;" : "=r"(mw) : "f"(r1), "f"(r0));
}

// =======================================================================
// Kernel 0: split fp32 -> 2 fp16 levels, pair-contiguous blocks (R14 form)
// =======================================================================
__global__ __launch_bounds__(256) void split_kernel(const float* __restrict__ x) {
    const size_t idx = (size_t)blockIdx.x * 256 + threadIdx.x;   // 8*1024*256 groups
    const int b   = (int)(idx >> 18);
    const int row = (int)((idx >> 8) & 1023);
    const int k16 = (int)(idx & 255);

    size_t src;
    if (row < CCH) src = ((size_t)b * CCH + row) * KDIM + (size_t)k16 * 16;
    else           src = ((size_t)(BATCH + b) * CCH + (row - CCH)) * KDIM + (size_t)k16 * 16;

    const int rb = row >> 7, r = row & 127;
    const int kb = k16 >> 2;
    const int pair = rb >> 1, half = rb & 1;
    char* blk = (char*)g_pack + ((((size_t)b * 4 + pair) * NKB) + kb) * (size_t)PAIRBLK
              + (size_t)half * IMG16;

    #pragma unroll
    for (int g = 0; g < 2; g++) {
        const float4 v0 = *(const float4*)(x + src + g * 8);
        const float4 v1 = *(const float4*)(x + src + g * 8 + 4);
        uint4 hv, mv;
        cvt2p(v0.x, v0.y, hv.x, mv.x);
        cvt2p(v0.z, v0.w, hv.y, mv.y);
        cvt2p(v1.x, v1.y, hv.z, mv.z);
        cvt2p(v1.z, v1.w, hv.w, mv.w);
        const uint32_t byte_off = (uint32_t)r * 128u + (uint32_t)((2 * k16 + g) & 7) * 16u;
        const uint32_t sw = byte_off ^ ((byte_off >> 3) & 0x70u);
        *(uint4*)(blk + sw)             = hv;
        *(uint4*)(blk + sw + 2 * IMG16) = mv;
    }
}

// =======================================================================
// Kernel A: ALL-cg2 fp16 3-term SYRK, 256x256 tile per 2-CTA cluster.
// Each CTA: A = its 128-row half (32K/stage), B = its 128-col half (32K;
// diag tiles: B==A, 32K total). 80 clusters = 160 CTAs, one wave.
//   t0  : producer (own A[,B])       t64 : own-full -> leader allfull (mapa)
//   t32 : cg2 MMA issuer (rank0)     warps 0-3: epilogue on own D half
// =======================================================================
#if TC_OK
__device__ __forceinline__ void mbar_init(uint32_t a, uint32_t cnt) {
    asm volatile("mbarrier.init.shared.b64 [%0], %1;" :: "r"(a), "r"(cnt) : "memory");
}
__device__ __forceinline__ void mbar_inval(uint32_t a) {
    asm volatile("mbarrier.inval.shared.b64 [%0];" :: "r"(a) : "memory");
}
__device__ __forceinline__ void mbar_expect_tx(uint32_t a, uint32_t bytes) {
    asm volatile("mbarrier.arrive.expect_tx.shared.b64 _, [%0], %1;" :: "r"(a), "r"(bytes) : "memory");
}
__device__ __forceinline__ void mbar_arrive_rank0(uint32_t local_addr) {
    asm volatile(
        "{\n\t.reg .b32 ra;\n\t"
        "mapa.shared::cluster.u32 ra, %0, 0;\n\t"
        "mbarrier.arrive.shared::cluster.b64 _, [ra];\n\t}"
        :: "r"(local_addr) : "memory");
}
__device__ __forceinline__ void mbar_wait(uint32_t a, uint32_t parity) {
    asm volatile(
        "{\n\t.reg .pred P;\n\t"
        "W%=:\n\t"
        "mbarrier.try_wait.parity.acquire.cta.shared::cta.b64 P, [%0], %1, 0x989680;\n\t"
        "@P bra.uni D%=;\n\t"
        "bra.uni W%=;\n\t"
        "D%=:\n\t}"
        :: "r"(a), "r"(parity) : "memory");
}
__device__ __forceinline__ void bulk_g2s(uint32_t dst, const void* src, uint32_t bytes, uint32_t mbar) {
    asm volatile(
        "cp.async.bulk.shared::cta.global.mbarrier::complete_tx::bytes [%0], [%1], %2, [%3];"
        :: "r"(dst), "l"(src), "r"(bytes), "r"(mbar) : "memory");
}
__device__ __forceinline__ uint64_t make_desc_sw128(uint32_t addr) {
    return ((uint64_t)2 << 61) | ((uint64_t)1 << 46) | ((uint64_t)64 << 32) |
           ((uint64_t)1 << 16) | (((uint64_t)(addr >> 4)) & 0x3FFF);
}
__device__ __forceinline__ void mma_f16_cg2(uint32_t d, uint64_t ad, uint64_t bd, uint32_t en) {
    asm volatile(
        "{\n\t.reg .pred p;\n\t"
        "setp.ne.u32 p, %5, 0;\n\t"
        "tcgen05.mma.cta_group::2.kind::f16 [%0], %1, %2, %3, {%4,%4,%4,%4,%4,%4,%4,%4}, p;\n\t}"
        :: "r"(d), "l"(ad), "l"(bd), "r"(IDESC_CG2), "r"(0u), "r"(en) : "memory");
}
__device__ __forceinline__ void tc_commit_cg2_mc(uint32_t mbar, uint16_t mask) {
    asm volatile(
        "tcgen05.commit.cta_group::2.mbarrier::arrive::one.shared::cluster.multicast::cluster.b64 [%0], %1;"
        :: "r"(mbar), "h"(mask) : "memory");
}
#endif

__global__ __launch_bounds__(128, 1) __cluster_dims__(2, 1, 1) void syrk_tc_kernel() {
#if TC_OK
    extern __shared__ char smem[];
    const uint32_t sb = smem_u32(smem);
    const uint32_t tb = (sb + 1023u) & ~1023u;
    const uint32_t ctl = tb + NSTAGES * STAGE_BYTES;
    const uint32_t mb_full    = ctl + 16;                 // 3 x 8B (own, tx)
    const uint32_t mb_allfull = ctl + 16 + 24;            // 3 x 8B (count 2, leader's)
    const uint32_t mb_empty   = ctl + 16 + 48;            // 3 x 8B (count 1)
    const uint32_t mb_done    = ctl + 16 + 72;

    const int tid = threadIdx.x;
    const int wid = tid >> 5, lid = tid & 31;

    const int bx = blockIdx.x;
    const int cl = bx >> 1;
    const int rank = bx & 1;
    const int b = cl / 10;
    const int t = cl - b * 10;
    const int ti = c_TI2[t], tj = c_TJ2[t];
    const bool diag = (ti == tj);

    // per-CTA flags: write/mirror per col-half {lo=pair tj rb0, hi=rb1}
    // off-diag: 0xF.  diag: rank0 -> 0xD (diag blk w, upper blk w+m); rank1 -> 0x4.
    const int fl = diag ? (rank == 0 ? 0xD : 0x4) : 0xF;

    if (wid == 0) {
        asm volatile("tcgen05.alloc.cta_group::2.sync.aligned.shared::cta.b32 [%0], %1;"
                     :: "r"(ctl), "r"(256u) : "memory");
    }
    if (tid == 0) {
        for (int s = 0; s < NSTAGES; s++) {
            mbar_init(mb_full + s * 8, 1);
            mbar_init(mb_allfull + s * 8, 2);
            mbar_init(mb_empty + s * 8, 1);
        }
        mbar_init(mb_done, 1);
        asm volatile("fence.proxy.async.shared::cta;" ::: "memory");
    }
    __syncthreads();
    asm volatile("barrier.cluster.arrive.aligned;" ::: "memory");
    asm volatile("barrier.cluster.wait.aligned;" ::: "memory");

    uint32_t tmem;
    asm volatile("ld.shared.b32 %0, [%1];" : "=r"(tmem) : "r"(ctl));

    const uint32_t txbytes = diag ? 32768u : 65536u;

    if (tid == 0) {
        // ---------------- producer: own A half (+ own B half if off-diag) ----------------
        const char* PA = (const char*)g_pack + (((size_t)b * 4 + ti) * NKB) * (size_t)PAIRBLK;
        const char* PB = (const char*)g_pack + (((size_t)b * 4 + tj) * NKB) * (size_t)PAIRBLK;
        const uint32_t hoff = (uint32_t)rank * IMG16;
        int ph[NSTAGES] = {0, 0, 0};
        for (int kb = 0; kb < NKB; kb++) {
            const int s = kb % NSTAGES;
            if (kb >= NSTAGES) { mbar_wait(mb_empty + s * 8, ph[s]); ph[s] ^= 1; }
            const uint32_t st = tb + s * STAGE_BYTES;
            const uint32_t fb = mb_full + s * 8;
            mbar_expect_tx(fb, txbytes);
            const char* sa = PA + (size_t)kb * PAIRBLK;
            bulk_g2s(st,         sa + hoff,             IMG16, fb);   // A.h (own half)
            bulk_g2s(st + 16384, sa + 2 * IMG16 + hoff, IMG16, fb);   // A.m
            if (!diag) {
                const char* sbp = PB + (size_t)kb * PAIRBLK;
                bulk_g2s(st + 32768, sbp + hoff,             IMG16, fb);   // B.h (own col half)
                bulk_g2s(st + 49152, sbp + 2 * IMG16 + hoff, IMG16, fb);   // B.m
            }
        }
    } else if (tid == 64) {
        // ---------------- forwarder: own full -> leader's allfull ----------------
        int ph[NSTAGES] = {0, 0, 0};
        for (int kb = 0; kb < NKB; kb++) {
            const int s = kb % NSTAGES;
            mbar_wait(mb_full + s * 8, ph[s]); ph[s] ^= 1;
            mbar_arrive_rank0(mb_allfull + s * 8);
        }
    } else if (tid == 32 && rank == 0) {
        // ---------------- cg2 MMA issuer (leader): hh, hm, mh ----------------
        int ph[NSTAGES] = {0, 0, 0};
        uint32_t en = 0;
        for (int kb = 0; kb < NKB; kb++) {
            const int s = kb % NSTAGES;
            mbar_wait(mb_allfull + s * 8, ph[s]); ph[s] ^= 1;
            const uint32_t st = tb + s * STAGE_BYTES;
            const uint64_t dAh = make_desc_sw128(st);
            const uint64_t dAm = make_desc_sw128(st + 16384);
            const uint64_t dBh = diag ? dAh : make_desc_sw128(st + 32768);
            const uint64_t dBm = diag ? dAm : make_desc_sw128(st + 49152);
            #pragma unroll
            for (int k = 0; k < 4; k++) {      // 4 k-steps of 16 fp16 (+2 units)
                const uint64_t o = k * 2;
                mma_f16_cg2(tmem, dAh + o, dBh + o, en); en = 1;
                mma_f16_cg2(tmem, dAh + o, dBm + o, 1);
                mma_f16_cg2(tmem, dAm + o, dBh + o, 1);
            }
            tc_commit_cg2_mc(mb_empty + s * 8, (uint16_t)3);
        }
        tc_commit_cg2_mc(mb_done, (uint16_t)3);
    }

    // ---------------- epilogue: own 128 rows x 256 cols of D ----------------
    mbar_wait(mb_done, 0);
    asm volatile("tcgen05.fence::after_thread_sync;" ::: "memory");

    const size_t Sb = (size_t)b * M2 * M2;
    const int i_rb = 2 * ti + rank;
    const int r0 = i_rb * 128;
    const int colbase = tj * 256;
    const int row = r0 + wid * 32 + lid;
    float* trsp = (float*)(smem + (tb - sb));

    for (int cb = 0; cb < 8; cb++) {
        const int half = cb >> 2;
        const int wbit = (fl >> (half * 2)) & 1;
        const int mbit = (fl >> (half * 2 + 1)) & 1;
        const int c0 = colbase + cb * 32;

        uint32_t d[32];
        asm volatile(
            "tcgen05.ld.sync.aligned.32x32b.x32.b32 "
            "{%0,%1,%2,%3,%4,%5,%6,%7,%8,%9,%10,%11,%12,%13,%14,%15,"
            "%16,%17,%18,%19,%20,%21,%22,%23,%24,%25,%26,%27,%28,%29,%30,%31}, [%32];"
            : "=r"(d[0]), "=r"(d[1]), "=r"(d[2]), "=r"(d[3]), "=r"(d[4]), "=r"(d[5]), "=r"(d[6]), "=r"(d[7]),
              "=r"(d[8]), "=r"(d[9]), "=r"(d[10]), "=r"(d[11]), "=r"(d[12]), "=r"(d[13]), "=r"(d[14]), "=r"(d[15]),
              "=r"(d[16]), "=r"(d[17]), "=r"(d[18]), "=r"(d[19]), "=r"(d[20]), "=r"(d[21]), "=r"(d[22]), "=r"(d[23]),
              "=r"(d[24]), "=r"(d[25]), "=r"(d[26]), "=r"(d[27]), "=r"(d[28]), "=r"(d[29]), "=r"(d[30]), "=r"(d[31])
            : "r"(tmem + cb * 32));
        asm volatile("tcgen05.wait::ld.sync.aligned;" ::: "memory");

        if (wbit) {
            float* dst = g_S + Sb + (size_t)row * M2 + c0;
            #pragma unroll
            for (int q = 0; q < 8; q++) {
                float4 v = make_float4(__uint_as_float(d[q * 4 + 0]), __uint_as_float(d[q * 4 + 1]),
                                       __uint_as_float(d[q * 4 + 2]), __uint_as_float(d[q * 4 + 3]));
                *(float4*)(dst + q * 4) = v;
            }
        }
        if (mbit) {
            const int lr = wid * 32 + lid;
            #pragma unroll
            for (int j = 0; j < 32; j++)
                trsp[j * 132 + lr] = __uint_as_float(d[j]);
            __syncthreads();
            const int mj = tid >> 2;
            const int ch = tid & 3;
            float* mdst = g_S + Sb + (size_t)(c0 + mj) * M2 + r0 + ch * 32;
            const float* msrc = trsp + mj * 132 + ch * 32;
            #pragma unroll
            for (int q = 0; q < 8; q++)
                *(float4*)(mdst + q * 4) = *(const float4*)(msrc + q * 4);
            __syncthreads();
        }
    }

    __syncthreads();
    if (tid == 0) {
        for (int s = 0; s < NSTAGES; s++) {
            mbar_inval(mb_full + s * 8); mbar_inval(mb_allfull + s * 8); mbar_inval(mb_empty + s * 8);
        }
        mbar_inval(mb_done);
    }
    __syncthreads();
    if (wid == 0) {
        asm volatile("tcgen05.relinquish_alloc_permit.cta_group::2.sync.aligned;");
        asm volatile("tcgen05.dealloc.cta_group::2.sync.aligned.b32 %0, %1;" :: "r"(tmem), "r"(256u));
    }
    asm volatile("barrier.cluster.arrive.aligned;" ::: "memory");
    asm volatile("barrier.cluster.wait.aligned;" ::: "memory");
#endif
}

// =======================================================================
// Kernel B: warp-per-row softmax + compaction (no block barriers).
// =======================================================================
__global__ __launch_bounds__(256) void attn_kernel() {
    const int warp = threadIdx.x >> 5, lane = threadIdx.x & 31;
    const int r = blockIdx.x * 8 + warp;
    const int b = r >> 9, c = r & 511;

    const float* S0 = g_S + ((size_t)b * M2 + c) * M2;
    const float* S1 = g_S + ((size_t)b * M2 + CCH + c) * M2;

    float er[16], ei[16];
    float mer = -3.4e38f, mei = -3.4e38f;
    #pragma unroll
    for (int i = 0; i < 16; i++) {
        const int d = i * 32 + lane;
        const float s00 = S0[d];
        const float s0h = S0[CCH + d];
        const float s10 = S1[d];
        const float s1h = S1[CCH + d];
        er[i] = s00 - s1h;
        ei[i] = s0h + s10;
        mer = fmaxf(mer, er[i]);
        mei = fmaxf(mei, ei[i]);
    }
    #pragma unroll
    for (int o = 16; o > 0; o >>= 1) {
        mer = fmaxf(mer, __shfl_xor_sync(0xffffffffu, mer, o));
        mei = fmaxf(mei, __shfl_xor_sync(0xffffffffu, mei, o));
    }

    float sc[16];
    float smax = -3.4e38f;
    #pragma unroll
    for (int i = 0; i < 16; i++) {
        const float ar = mer - er[i];
        const float ai = mei - ei[i];
        sc[i] = ar * ar + ai * ai;
        smax = fmaxf(smax, sc[i]);
    }
    #pragma unroll
    for (int o = 16; o > 0; o >>= 1)
        smax = fmaxf(smax, __shfl_xor_sync(0xffffffffu, smax, o));

    float Z = 0.0f;
    #pragma unroll
    for (int i = 0; i < 16; i++) {
        sc[i] = expf(sc[i] - smax);
        Z += sc[i];
    }
    #pragma unroll
    for (int o = 16; o > 0; o >>= 1)
        Z += __shfl_xor_sync(0xffffffffu, Z, o);
    const float invZ = 1.0f / Z;

    int cntl = 0;
    #pragma unroll
    for (int i = 0; i < 16; i++) {
        sc[i] *= invZ;
        if (sc[i] > 1e-10f) cntl++;
    }
    int incl = cntl;
    #pragma unroll
    for (int o = 1; o < 32; o <<= 1) {
        const int v = __shfl_up_sync(0xffffffffu, incl, o);
        if (lane >= o) incl += v;
    }
    const int total = __shfl_sync(0xffffffffu, incl, 31);
    int pos = incl - cntl;
    const size_t lbase = (size_t)r * CCH;
    #pragma unroll
    for (int i = 0; i < 16; i++) {
        if (sc[i] > 1e-10f) {
            g_idx[lbase + pos] = (unsigned short)(i * 32 + lane);
            g_w[lbase + pos] = sc[i];
            pos++;
        }
    }
    if (lane == 0) g_cnt[r] = total;
}

// =======================================================================
// Kernel C: out = gamma * (sparse attention @ q) + x
// =======================================================================
__global__ __launch_bounds__(256) void apply_kernel(const float* __restrict__ x,
                                                    const float* __restrict__ gamma,
                                                    float* __restrict__ out) {
    const int r = blockIdx.x;
    const int b = r >> 9, c = r & 511;
    const int n = blockIdx.y * 1024 + threadIdx.x * 4;

    const int cnt = g_cnt[r];
    const float g = gamma[0];
    const size_t imagOff = (size_t)BATCH * CCH * KDIM;
    const float* xr = x;
    const float* xi = x + imagOff;

    float4 ar = make_float4(0.f, 0.f, 0.f, 0.f);
    float4 ai = make_float4(0.f, 0.f, 0.f, 0.f);
    const size_t lbase = (size_t)r * CCH;

    for (int i = 0; i < cnt; i++) {
        const int dch = g_idx[lbase + i];
        const float w = g_w[lbase + i];
        const size_t q = ((size_t)b * CCH + dch) * KDIM + n;
        const float4 qr = *(const float4*)(xr + q);
        const float4 qi = *(const float4*)(xi + q);
        ar.x += w * qr.x; ar.y += w * qr.y; ar.z += w * qr.z; ar.w += w * qr.w;
        ai.x += w * qi.x; ai.y += w * qi.y; ai.z += w * qi.z; ai.w += w * qi.w;
    }

    const size_t o = ((size_t)b * CCH + c) * KDIM + n;
    const float4 xrv = *(const float4*)(xr + o);
    const float4 xiv = *(const float4*)(xi + o);
    float4 orr = make_float4(g * ar.x + xrv.x, g * ar.y + xrv.y,
                             g * ar.z + xrv.z, g * ar.w + xrv.w);
    float4 oii = make_float4(g * ai.x + xiv.x, g * ai.y + xiv.y,
                             g * ai.z + xiv.z, g * ai.w + xiv.w);
    *(float4*)(out + o) = orr;
    *(float4*)(out + imagOff + o) = oii;
}

// =======================================================================
extern "C" void kernel_launch(void* const* d_in, const int* in_sizes, int n_in,
                              void* d_out, int out_size) {
    const float* x = (const float*)d_in[0];
    const float* gamma = (const float*)d_in[1];
    float* out = (float*)d_out;

    const int SMEM_DYN = 1024 + NSTAGES * STAGE_BYTES + 256;   // ~193.5 KB
    cudaFuncSetAttribute(syrk_tc_kernel, cudaFuncAttributeMaxDynamicSharedMemorySize, SMEM_DYN);

    split_kernel<<<(BATCH * 1024 * 256) / 256, 256>>>(x);
    syrk_tc_kernel<<<160, 128, SMEM_DYN>>>();
    attn_kernel<<<512, 256>>>();
    apply_kernel<<<dim3(BATCH * CCH, 4), 256>>>(x, gamma, out);
}

// round 17
// speedup vs baseline: 1.3954x; 1.2429x over previous
#include <cuda_runtime.h>
#include <cuda_fp16.h>
#include <cstdint>
#include <cstddef>

#define BATCH 8
#define CCH   512
#define M2    1024          // 2*C rows of P
#define KDIM  4096
#define NSTAGES 2
#define IMG16 16384                     // one 128-row fp16 level image (16KB)
#define PAIRBLK 65536                   // per (b,pair,kb): {h_lo,h_hi,m_lo,m_hi}
#define STAGE_BYTES 98304               // B(64K) + A(32K)
#define NKB   (KDIM / 64)               // 64 k-blocks of 64 elems

// idesc kind::f16 fp16: dtype F32 (1<<4) | (N/8)<<17 | (M/16)<<24  (M=128)
#define IDESC_N256 0x08400010u
#define IDESC_N128 0x08200010u

#if defined(__CUDA_ARCH__) && (defined(__CUDA_ARCH_FEAT_SM103_ALL) || defined(__CUDA_ARCH_FEAT_SM100_ALL) || defined(__CUDA_ARCH_FEAT_SM101_ALL) || defined(__CUDA_ARCH_FEAT_SM110_ALL))
#define TC_OK 1
#else
#define TC_OK 0
#endif

// ---------------- scratch (static device globals; no allocation) ----------------
__device__ uint32_t       g_pack[(size_t)BATCH * 4 * NKB * 16384];  // 134 MB
__device__ float          g_S[(size_t)BATCH * M2 * M2];             // 32 MB  S = P P^T
__device__ float          g_w[(size_t)BATCH * CCH * CCH];
__device__ unsigned short g_idx[(size_t)BATCH * CCH * CCH];
__device__ int            g_cnt[BATCH * CCH];

// heavy tiles (16/batch): 4x T1 (i=2k, colpair k, A inside B) + 12x inter.
// flags bit0 wlo, bit1 mlo, bit2 whi, bit3 mhi.
__constant__ unsigned char c_hI[16]  = {0,2,4,6, 2,3,4,5, 4,5,6,7, 6,7,6,7};
__constant__ unsigned char c_hJ[16]  = {0,1,2,3, 0,0,0,0, 1,1,0,0, 1,1,2,2};
__constant__ unsigned char c_hFL[16] = {0xD,0xD,0xD,0xD, 0xF,0xF,0xF,0xF,
                                        0xF,0xF,0xF,0xF, 0xF,0xF,0xF,0xF};

// ======================= helpers =======================
__device__ __forceinline__ uint32_t smem_u32(const void* p) {
    uint32_t a;
    asm("{ .reg .u64 t; cvta.to.shared.u64 t, %1; cvt.u32.u64 %0, t; }" : "=r"(a) : "l"(p));
    return a;
}

__device__ __forceinline__ void cvt2p(float e0, float e1, uint32_t& hw, uint32_t& mw) {
    asm("cvt.rn.f16x2.f32 %0, %1, %2;" : "=r"(hw) : "f"(e1), "f"(e0));
    const __half2 hp = *reinterpret_cast<const __half2*>(&hw);
    const float2 hf = __half22float2(hp);
    const float r0 = e0 - hf.x, r1 = e1 - hf.y;
    asm("cvt.rn.f16x2.f32 %0, %1, %2;" : "=r"(mw) : "f"(r1), "f"(r0));
}

// =======================================================================
// Kernel 0: split fp32 -> 2 fp16 levels, pair-contiguous blocks.
// Each thread handles 16 consecutive elements (2 groups of 8, same kb).
// =======================================================================
__global__ __launch_bounds__(256) void split_kernel(const float* __restrict__ x) {
    const size_t idx = (size_t)blockIdx.x * 256 + threadIdx.x;   // 8*1024*256 pair-groups
    const int b   = (int)(idx >> 18);
    const int row = (int)((idx >> 8) & 1023);
    const int k16 = (int)(idx & 255);                            // group of 16 elems

    size_t src;
    if (row < CCH) src = ((size_t)b * CCH + row) * KDIM + (size_t)k16 * 16;
    else           src = ((size_t)(BATCH + b) * CCH + (row - CCH)) * KDIM + (size_t)k16 * 16;

    const int rb = row >> 7, r = row & 127;
    const int kb = k16 >> 2;                              // 2*k16 >> 3
    const int pair = rb >> 1, half = rb & 1;
    char* blk = (char*)g_pack + ((((size_t)b * 4 + pair) * NKB) + kb) * (size_t)PAIRBLK
              + (size_t)half * IMG16;

    #pragma unroll
    for (int g = 0; g < 2; g++) {
        const float4 v0 = *(const float4*)(x + src + g * 8);
        const float4 v1 = *(const float4*)(x + src + g * 8 + 4);
        uint4 hv, mv;
        cvt2p(v0.x, v0.y, hv.x, mv.x);
        cvt2p(v0.z, v0.w, hv.y, mv.y);
        cvt2p(v1.x, v1.y, hv.z, mv.z);
        cvt2p(v1.z, v1.w, hv.w, mv.w);
        const uint32_t byte_off = (uint32_t)r * 128u + (uint32_t)((2 * k16 + g) & 7) * 16u;
        const uint32_t sw = byte_off ^ ((byte_off >> 3) & 0x70u);
        *(uint4*)(blk + sw)             = hv;
        *(uint4*)(blk + sw + 2 * IMG16) = mv;
    }
}

// =======================================================================
// Kernel A: tcgen05 fp16 3-term SYRK (hh+hm+mh). 160 CTAs, cg1, heavy-first.
// Producer additionally L2-prefetches stage kb+2's sources (latency hiding).
// =======================================================================
#if TC_OK
__device__ __forceinline__ void mbar_init(uint32_t a, uint32_t cnt) {
    asm volatile("mbarrier.init.shared.b64 [%0], %1;" :: "r"(a), "r"(cnt) : "memory");
}
__device__ __forceinline__ void mbar_inval(uint32_t a) {
    asm volatile("mbarrier.inval.shared.b64 [%0];" :: "r"(a) : "memory");
}
__device__ __forceinline__ void mbar_expect_tx(uint32_t a, uint32_t bytes) {
    asm volatile("mbarrier.arrive.expect_tx.shared.b64 _, [%0], %1;" :: "r"(a), "r"(bytes) : "memory");
}
__device__ __forceinline__ void mbar_wait(uint32_t a, uint32_t parity) {
    asm volatile(
        "{\n\t.reg .pred P;\n\t"
        "W%=:\n\t"
        "mbarrier.try_wait.parity.acquire.cta.shared::cta.b64 P, [%0], %1, 0x989680;\n\t"
        "@P bra.uni D%=;\n\t"
        "bra.uni W%=;\n\t"
        "D%=:\n\t}"
        :: "r"(a), "r"(parity) : "memory");
}
__device__ __forceinline__ void bulk_g2s(uint32_t dst, const void* src, uint32_t bytes, uint32_t mbar) {
    asm volatile(
        "cp.async.bulk.shared::cta.global.mbarrier::complete_tx::bytes [%0], [%1], %2, [%3];"
        :: "r"(dst), "l"(src), "r"(bytes), "r"(mbar) : "memory");
}
__device__ __forceinline__ void l2_prefetch(const void* src, uint32_t bytes) {
    asm volatile("cp.async.bulk.prefetch.L2.global [%0], %1;" :: "l"(src), "r"(bytes) : "memory");
}
__device__ __forceinline__ uint64_t make_desc_sw128(uint32_t addr) {
    return ((uint64_t)2 << 61) | ((uint64_t)1 << 46) | ((uint64_t)64 << 32) |
           ((uint64_t)1 << 16) | (((uint64_t)(addr >> 4)) & 0x3FFF);
}
__device__ __forceinline__ void mma_f16(uint32_t d, uint64_t ad, uint64_t bd, uint32_t idesc, uint32_t en) {
    asm volatile(
        "{\n\t.reg .pred p;\n\t"
        "setp.ne.u32 p, %5, 0;\n\t"
        "tcgen05.mma.cta_group::1.kind::f16 [%0], %1, %2, %3, {%4,%4,%4,%4}, p;\n\t}"
        :: "r"(d), "l"(ad), "l"(bd), "r"(idesc), "r"(0u), "r"(en) : "memory");
}
__device__ __forceinline__ void tc_commit(uint32_t mbar) {
    asm volatile(
        "tcgen05.commit.cta_group::1.mbarrier::arrive::one.shared::cluster.b64 [%0];"
        :: "r"(mbar) : "memory");
}
#endif

__global__ __launch_bounds__(128, 1) void syrk_tc_kernel() {
#if TC_OK
    extern __shared__ char smem[];
    const uint32_t sb = smem_u32(smem);
    const uint32_t tb = (sb + 1023u) & ~1023u;
    const uint32_t ctl = tb + NSTAGES * STAGE_BYTES;
    const uint32_t mb_full  = ctl + 16;                   // 2 x 8B
    const uint32_t mb_empty = ctl + 16 + 16;              // 2 x 8B
    const uint32_t mb_done  = ctl + 16 + 32;

    const int tid = threadIdx.x;
    const int wid = tid >> 5, lid = tid & 31;

    const int bx = blockIdx.x;
    int b, i, J, fl, typ;      // typ: 0 = T1 heavy, 1 = inter heavy, 2 = light
    if (bx < 128) {
        b = bx >> 4;
        const int t = bx & 15;
        i = c_hI[t]; J = c_hJ[t]; fl = c_hFL[t];
        typ = (t < 4) ? 0 : 1;
    } else {
        const int q = bx - 128;
        b = q >> 2;
        i = (q & 3) * 2 + 1;
        J = i;
        fl = 0x1;
        typ = 2;
    }
    const bool heavy = (typ <= 1);
    const uint32_t idesc = heavy ? IDESC_N256 : IDESC_N128;
    const uint32_t txbytes = (typ == 1) ? 98304u : (typ == 0 ? 65536u : 32768u);

    if (wid == 0) {
        asm volatile("tcgen05.alloc.cta_group::1.sync.aligned.shared::cta.b32 [%0], %1;"
                     :: "r"(ctl), "r"(256u) : "memory");
    }
    if (tid == 0) {
        for (int s = 0; s < NSTAGES; s++) { mbar_init(mb_full + s * 8, 1); mbar_init(mb_empty + s * 8, 1); }
        mbar_init(mb_done, 1);
        asm volatile("fence.proxy.async.shared::cta;" ::: "memory");
    }
    __syncthreads();

    uint32_t tmem;
    asm volatile("ld.shared.b32 %0, [%1];" : "=r"(tmem) : "r"(ctl));

    if (tid == 0) {
        // ---------------- producer (with +2-stage L2 prefetch) ----------------
        const char* PB = (const char*)g_pack +
            (((size_t)b * 4 + (heavy ? J : (i >> 1))) * NKB) * (size_t)PAIRBLK;
        const char* PA = (const char*)g_pack +
            (((size_t)b * 4 + (i >> 1)) * NKB) * (size_t)PAIRBLK;
        const uint32_t ahalf = (uint32_t)(i & 1) * IMG16;
        int ph[NSTAGES] = {0, 0};

        // warm L2 for the first two stages
        #pragma unroll
        for (int pf = 0; pf < 2; pf++) {
            if (typ == 2) {
                l2_prefetch(PB + (size_t)pf * PAIRBLK + IMG16,     IMG16);
                l2_prefetch(PB + (size_t)pf * PAIRBLK + 3 * IMG16, IMG16);
            } else {
                l2_prefetch(PB + (size_t)pf * PAIRBLK, PAIRBLK);
                if (typ == 1) {
                    l2_prefetch(PA + (size_t)pf * PAIRBLK + ahalf,             IMG16);
                    l2_prefetch(PA + (size_t)pf * PAIRBLK + 2 * IMG16 + ahalf, IMG16);
                }
            }
        }

        for (int kb = 0; kb < NKB; kb++) {
            const int s = kb & 1;
            if (kb >= NSTAGES) { mbar_wait(mb_empty + s * 8, ph[s]); ph[s] ^= 1; }
            const uint32_t st = tb + s * STAGE_BYTES;
            const uint32_t fb = mb_full + s * 8;
            mbar_expect_tx(fb, txbytes);
            if (typ == 2) {
                bulk_g2s(st,          PB + (size_t)kb * PAIRBLK + IMG16,     IMG16, fb);
                bulk_g2s(st + 32768,  PB + (size_t)kb * PAIRBLK + 3 * IMG16, IMG16, fb);
            } else {
                bulk_g2s(st, PB + (size_t)kb * PAIRBLK, PAIRBLK, fb);     // B: h(32K)+m(32K)
                if (typ == 1) {
                    bulk_g2s(st + 65536, PA + (size_t)kb * PAIRBLK + ahalf,             IMG16, fb);
                    bulk_g2s(st + 81920, PA + (size_t)kb * PAIRBLK + 2 * IMG16 + ahalf, IMG16, fb);
                }
            }
            // prefetch stage kb+2 into L2 (pure hint; hides DRAM latency)
            const int pf = kb + 2;
            if (pf < NKB) {
                if (typ == 2) {
                    l2_prefetch(PB + (size_t)pf * PAIRBLK + IMG16,     IMG16);
                    l2_prefetch(PB + (size_t)pf * PAIRBLK + 3 * IMG16, IMG16);
                } else {
                    l2_prefetch(PB + (size_t)pf * PAIRBLK, PAIRBLK);
                    if (typ == 1) {
                        l2_prefetch(PA + (size_t)pf * PAIRBLK + ahalf,             IMG16);
                        l2_prefetch(PA + (size_t)pf * PAIRBLK + 2 * IMG16 + ahalf, IMG16);
                    }
                }
            }
        }
    } else if (tid == 32) {
        // ---------------- MMA issuer: 3 terms (hh, hm, mh) ----------------
        int ph[NSTAGES] = {0, 0};
        uint32_t en = 0;
        for (int kb = 0; kb < NKB; kb++) {
            const int s = kb & 1;
            mbar_wait(mb_full + s * 8, ph[s]); ph[s] ^= 1;
            const uint32_t st = tb + s * STAGE_BYTES;
            const uint64_t dBh = make_desc_sw128(st);
            const uint64_t dBm = make_desc_sw128(st + 32768);
            const uint64_t dAh = (typ == 1) ? make_desc_sw128(st + 65536) : dBh;
            const uint64_t dAm = (typ == 1) ? make_desc_sw128(st + 81920) : dBm;
            #pragma unroll
            for (int k = 0; k < 4; k++) {
                const uint64_t o = k * 2;
                mma_f16(tmem, dAh + o, dBh + o, idesc, en); en = 1;
                mma_f16(tmem, dAh + o, dBm + o, idesc, 1);
                mma_f16(tmem, dAm + o, dBh + o, idesc, 1);
            }
            tc_commit(mb_empty + s * 8);
        }
        tc_commit(mb_done);
    }

    // ---------------- epilogue ----------------
    mbar_wait(mb_done, 0);
    asm volatile("tcgen05.fence::after_thread_sync;" ::: "memory");

    const size_t Sb = (size_t)b * M2 * M2;
    const int r0 = i * 128;
    const int colbase = heavy ? J * 256 : i * 128;
    const int nch = heavy ? 8 : 4;
    const int row = r0 + wid * 32 + lid;
    float* trsp = (float*)(smem + (tb - sb));

    for (int cb = 0; cb < nch; cb++) {
        const int half = heavy ? (cb >> 2) : 0;
        const int wbit = (fl >> (half * 2)) & 1;
        const int mbit = (fl >> (half * 2 + 1)) & 1;
        const int c0 = colbase + cb * 32;

        uint32_t d[32];
        asm volatile(
            "tcgen05.ld.sync.aligned.32x32b.x32.b32 "
            "{%0,%1,%2,%3,%4,%5,%6,%7,%8,%9,%10,%11,%12,%13,%14,%15,"
            "%16,%17,%18,%19,%20,%21,%22,%23,%24,%25,%26,%27,%28,%29,%30,%31}, [%32];"
            : "=r"(d[0]), "=r"(d[1]), "=r"(d[2]), "=r"(d[3]), "=r"(d[4]), "=r"(d[5]), "=r"(d[6]), "=r"(d[7]),
              "=r"(d[8]), "=r"(d[9]), "=r"(d[10]), "=r"(d[11]), "=r"(d[12]), "=r"(d[13]), "=r"(d[14]), "=r"(d[15]),
              "=r"(d[16]), "=r"(d[17]), "=r"(d[18]), "=r"(d[19]), "=r"(d[20]), "=r"(d[21]), "=r"(d[22]), "=r"(d[23]),
              "=r"(d[24]), "=r"(d[25]), "=r"(d[26]), "=r"(d[27]), "=r"(d[28]), "=r"(d[29]), "=r"(d[30]), "=r"(d[31])
            : "r"(tmem + cb * 32));
        asm volatile("tcgen05.wait::ld.sync.aligned;" ::: "memory");

        if (wbit) {
            float* dst = g_S + Sb + (size_t)row * M2 + c0;
            #pragma unroll
            for (int q = 0; q < 8; q++) {
                float4 v = make_float4(__uint_as_float(d[q * 4 + 0]), __uint_as_float(d[q * 4 + 1]),
                                       __uint_as_float(d[q * 4 + 2]), __uint_as_float(d[q * 4 + 3]));
                *(float4*)(dst + q * 4) = v;
            }
        }
        if (mbit) {
            const int lr = wid * 32 + lid;
            #pragma unroll
            for (int j = 0; j < 32; j++)
                trsp[j * 132 + lr] = __uint_as_float(d[j]);
            __syncthreads();
            const int mj = tid >> 2;
            const int ch = tid & 3;
            float* mdst = g_S + Sb + (size_t)(c0 + mj) * M2 + r0 + ch * 32;
            const float* msrc = trsp + mj * 132 + ch * 32;
            #pragma unroll
            for (int q = 0; q < 8; q++)
                *(float4*)(mdst + q * 4) = *(const float4*)(msrc + q * 4);
            __syncthreads();
        }
    }

    __syncthreads();
    if (tid == 0) {
        for (int s = 0; s < NSTAGES; s++) { mbar_inval(mb_full + s * 8); mbar_inval(mb_empty + s * 8); }
        mbar_inval(mb_done);
    }
    __syncthreads();
    if (wid == 0) {
        asm volatile("tcgen05.dealloc.cta_group::1.sync.aligned.b32 %0, %1;" :: "r"(tmem), "r"(256u));
    }
#endif
}

// =======================================================================
// Kernel B: warp-per-row softmax + compaction (no block barriers).
// =======================================================================
__global__ __launch_bounds__(256) void attn_kernel() {
    const int warp = threadIdx.x >> 5, lane = threadIdx.x & 31;
    const int r = blockIdx.x * 8 + warp;
    const int b = r >> 9, c = r & 511;

    const float* S0 = g_S + ((size_t)b * M2 + c) * M2;
    const float* S1 = g_S + ((size_t)b * M2 + CCH + c) * M2;

    float er[16], ei[16];
    float mer = -3.4e38f, mei = -3.4e38f;
    #pragma unroll
    for (int i = 0; i < 16; i++) {
        const int d = i * 32 + lane;
        const float s00 = S0[d];
        const float s0h = S0[CCH + d];
        const float s10 = S1[d];
        const float s1h = S1[CCH + d];
        er[i] = s00 - s1h;
        ei[i] = s0h + s10;
        mer = fmaxf(mer, er[i]);
        mei = fmaxf(mei, ei[i]);
    }
    #pragma unroll
    for (int o = 16; o > 0; o >>= 1) {
        mer = fmaxf(mer, __shfl_xor_sync(0xffffffffu, mer, o));
        mei = fmaxf(mei, __shfl_xor_sync(0xffffffffu, mei, o));
    }

    float sc[16];
    float smax = -3.4e38f;
    #pragma unroll
    for (int i = 0; i < 16; i++) {
        const float ar = mer - er[i];
        const float ai = mei - ei[i];
        sc[i] = ar * ar + ai * ai;
        smax = fmaxf(smax, sc[i]);
    }
    #pragma unroll
    for (int o = 16; o > 0; o >>= 1)
        smax = fmaxf(smax, __shfl_xor_sync(0xffffffffu, smax, o));

    float Z = 0.0f;
    #pragma unroll
    for (int i = 0; i < 16; i++) {
        sc[i] = expf(sc[i] - smax);
        Z += sc[i];
    }
    #pragma unroll
    for (int o = 16; o > 0; o >>= 1)
        Z += __shfl_xor_sync(0xffffffffu, Z, o);
    const float invZ = 1.0f / Z;

    int cntl = 0;
    #pragma unroll
    for (int i = 0; i < 16; i++) {
        sc[i] *= invZ;
        if (sc[i] > 1e-10f) cntl++;
    }
    int incl = cntl;
    #pragma unroll
    for (int o = 1; o < 32; o <<= 1) {
        const int v = __shfl_up_sync(0xffffffffu, incl, o);
        if (lane >= o) incl += v;
    }
    const int total = __shfl_sync(0xffffffffu, incl, 31);
    int pos = incl - cntl;
    const size_t lbase = (size_t)r * CCH;
    #pragma unroll
    for (int i = 0; i < 16; i++) {
        if (sc[i] > 1e-10f) {
            g_idx[lbase + pos] = (unsigned short)(i * 32 + lane);
            g_w[lbase + pos] = sc[i];
            pos++;
        }
    }
    if (lane == 0) g_cnt[r] = total;
}

// =======================================================================
// Kernel C: out = gamma * (sparse attention @ q) + x
// =======================================================================
__global__ __launch_bounds__(256) void apply_kernel(const float* __restrict__ x,
                                                    const float* __restrict__ gamma,
                                                    float* __restrict__ out) {
    const int r = blockIdx.x;
    const int b = r >> 9, c = r & 511;
    const int n = blockIdx.y * 1024 + threadIdx.x * 4;

    const int cnt = g_cnt[r];
    const float g = gamma[0];
    const size_t imagOff = (size_t)BATCH * CCH * KDIM;
    const float* xr = x;
    const float* xi = x + imagOff;

    float4 ar = make_float4(0.f, 0.f, 0.f, 0.f);
    float4 ai = make_float4(0.f, 0.f, 0.f, 0.f);
    const size_t lbase = (size_t)r * CCH;

    for (int i = 0; i < cnt; i++) {
        const int dch = g_idx[lbase + i];
        const float w = g_w[lbase + i];
        const size_t q = ((size_t)b * CCH + dch) * KDIM + n;
        const float4 qr = *(const float4*)(xr + q);
        const float4 qi = *(const float4*)(xi + q);
        ar.x += w * qr.x; ar.y += w * qr.y; ar.z += w * qr.z; ar.w += w * qr.w;
        ai.x += w * qi.x; ai.y += w * qi.y; ai.z += w * qi.z; ai.w += w * qi.w;
    }

    const size_t o = ((size_t)b * CCH + c) * KDIM + n;
    const float4 xrv = *(const float4*)(xr + o);
    const float4 xiv = *(const float4*)(xi + o);
    float4 orr = make_float4(g * ar.x + xrv.x, g * ar.y + xrv.y,
                             g * ar.z + xrv.z, g * ar.w + xrv.w);
    float4 oii = make_float4(g * ai.x + xiv.x, g * ai.y + xiv.y,
                             g * ai.z + xiv.z, g * ai.w + xiv.w);
    *(float4*)(out + o) = orr;
    *(float4*)(out + imagOff + o) = oii;
}

// =======================================================================
extern "C" void kernel_launch(void* const* d_in, const int* in_sizes, int n_in,
                              void* d_out, int out_size) {
    const float* x = (const float*)d_in[0];
    const float* gamma = (const float*)d_in[1];
    float* out = (float*)d_out;

    const int SMEM_DYN = 1024 + NSTAGES * STAGE_BYTES + 256;   // ~197.9 KB
    cudaFuncSetAttribute(syrk_tc_kernel, cudaFuncAttributeMaxDynamicSharedMemorySize, SMEM_DYN);

    split_kernel<<<(BATCH * 1024 * 256) / 256, 256>>>(x);
    syrk_tc_kernel<<<160, 128, SMEM_DYN>>>();
    attn_kernel<<<512, 256>>>();
    apply_kernel<<<dim3(BATCH * CCH, 4), 256>>>(x, gamma, out);
}